// round 10
// baseline (speedup 1.0000x reference)
#include <cuda_runtime.h>
#include <cuda_bf16.h>
#include <cstdint>

// World-model (confirmed, rel_err = 0.0):
//   d_in[0] = res  : float32 [M, N, D]   d_in[1] = h_pre: float32 [M, N]
//   d_out   = out  : float32 [M, D]
// out[m,d] = f32( bf16_round( sum_n res[m,n,d] * h[m,n] ) ), fp32 accum.
//
// R7: 186.3us (DRAM 91.5%, HBM 7.25TB/s). R8 streaming hints: NEUTRAL.
// R9 change: persistent grid-stride CTAs (592 = 148 SM x 4) — one wave,
// no wave-transition cost, cross-iteration load/store overlap.
static constexpr int M_DIM = 16384;
static constexpr int N_DIM = 4;
static constexpr int D_DIM = 4096;
static constexpr long long RES_ELEMS = (long long)M_DIM * N_DIM * D_DIM;

static constexpr int THREADS = 512;
static constexpr int GRID    = 592;   // 148 SMs x 4 resident CTAs of 512 thr

__global__ void __launch_bounds__(THREADS)
mhc_wsum_persistent_kernel(const float* __restrict__ res,
                           const float* __restrict__ h_pre,
                           float* __restrict__ out)
{
    const int t  = threadIdx.x;        // 0..511
    const int d0 = t * 8;              // 8 consecutive f32 per thread

    for (int m = blockIdx.x; m < M_DIM; m += GRID) {
        // Per-row weights (16 B, L1-broadcast across the CTA).
        const float4 w4 = *reinterpret_cast<const float4*>(h_pre + (size_t)m * N_DIM);

        const float* base = res + (size_t)m * N_DIM * D_DIM + d0;

        // 8 independent 128-bit loads, front-batched (MLP = 8).
        float4 v[N_DIM][2];
#pragma unroll
        for (int n = 0; n < N_DIM; ++n) {
            const float4* p = reinterpret_cast<const float4*>(base + (size_t)n * D_DIM);
            v[n][0] = p[0];
            v[n][1] = p[1];
        }

        float acc[8] = {0,0,0,0,0,0,0,0};
        const float w[4] = {w4.x, w4.y, w4.z, w4.w};
#pragma unroll
        for (int n = 0; n < N_DIM; ++n) {
            const float wn = w[n];
            acc[0] = fmaf(v[n][0].x, wn, acc[0]);
            acc[1] = fmaf(v[n][0].y, wn, acc[1]);
            acc[2] = fmaf(v[n][0].z, wn, acc[2]);
            acc[3] = fmaf(v[n][0].w, wn, acc[3]);
            acc[4] = fmaf(v[n][1].x, wn, acc[4]);
            acc[5] = fmaf(v[n][1].y, wn, acc[5]);
            acc[6] = fmaf(v[n][1].z, wn, acc[6]);
            acc[7] = fmaf(v[n][1].w, wn, acc[7]);
        }

        // Round through bf16 (reference .astype(bfloat16)), widen to f32.
        float4 o0, o1;
        o0.x = __bfloat162float(__float2bfloat16_rn(acc[0]));
        o0.y = __bfloat162float(__float2bfloat16_rn(acc[1]));
        o0.z = __bfloat162float(__float2bfloat16_rn(acc[2]));
        o0.w = __bfloat162float(__float2bfloat16_rn(acc[3]));
        o1.x = __bfloat162float(__float2bfloat16_rn(acc[4]));
        o1.y = __bfloat162float(__float2bfloat16_rn(acc[5]));
        o1.z = __bfloat162float(__float2bfloat16_rn(acc[6]));
        o1.w = __bfloat162float(__float2bfloat16_rn(acc[7]));

        float4* o = reinterpret_cast<float4*>(out + (size_t)m * D_DIM + d0);
        o[0] = o0;
        o[1] = o1;
        // Store has no consumer -> next iteration's loads issue immediately;
        // memory pipe stays full across row boundaries.
    }
}

extern "C" void kernel_launch(void* const* d_in, const int* in_sizes, int n_in,
                              void* d_out, int out_size)
{
    const float* res;
    const float* h;
    if ((long long)in_sizes[0] == RES_ELEMS) {
        res = (const float*)d_in[0];
        h   = (const float*)d_in[1];
    } else {
        res = (const float*)d_in[1];
        h   = (const float*)d_in[0];
    }

    float* out = (float*)d_out;
    mhc_wsum_persistent_kernel<<<GRID, THREADS>>>(res, h, out);
}

// round 12
// speedup vs baseline: 1.3624x; 1.3624x over previous
#include <cuda_runtime.h>
#include <cuda_bf16.h>
#include <cstdint>

// World-model (confirmed, rel_err = 0.0):
//   d_in[0] = res  : float32 [M, N, D]   d_in[1] = h_pre: float32 [M, N]
//   d_out   = out  : float32 [M, D]
// out[m,d] = f32( bf16_round( sum_n res[m,n,d] * h[m,n] ) ), fp32 accum.
//
// History: R7 186.3us (DRAM 91.5%, HBM 7.25TB/s) fire-and-forget 1 row/CTA.
//          R8 streaming hints NEUTRAL. R9 persistent CTAs FAILED (262us,
//          DRAM 64% — loop-carried scoreboard serialization).
// R10: keep fire-and-forget shape, 2 rows/CTA -> 16 front-batched LDG.128
//      per thread (MLP 16), zero loop-carried deps.
static constexpr int M_DIM = 16384;
static constexpr int N_DIM = 4;
static constexpr int D_DIM = 4096;
static constexpr long long RES_ELEMS = (long long)M_DIM * N_DIM * D_DIM;
static constexpr int ROWS_PER_CTA = 2;

__global__ void __launch_bounds__(512)
mhc_wsum_f32x2_kernel(const float* __restrict__ res,
                      const float* __restrict__ h_pre,
                      float* __restrict__ out)
{
    const int m0 = blockIdx.x * ROWS_PER_CTA;   // rows m0, m0+1
    const int t  = threadIdx.x;                 // 0..511
    const int d0 = t * 8;                       // 8 consecutive f32 per thread

    // Weights for both rows (32 B, L1-broadcast).
    const float4 wa = *reinterpret_cast<const float4*>(h_pre + (size_t)m0 * N_DIM);
    const float4 wb = *reinterpret_cast<const float4*>(h_pre + (size_t)(m0 + 1) * N_DIM);

    const float* baseA = res + (size_t)m0 * N_DIM * D_DIM + d0;
    const float* baseB = baseA + (size_t)N_DIM * D_DIM;

    // Front-batch ALL 16 independent 128-bit loads (MLP = 16, no deps).
    float4 va[N_DIM][2], vb[N_DIM][2];
#pragma unroll
    for (int n = 0; n < N_DIM; ++n) {
        const float4* pa = reinterpret_cast<const float4*>(baseA + (size_t)n * D_DIM);
        va[n][0] = pa[0];
        va[n][1] = pa[1];
    }
#pragma unroll
    for (int n = 0; n < N_DIM; ++n) {
        const float4* pb = reinterpret_cast<const float4*>(baseB + (size_t)n * D_DIM);
        vb[n][0] = pb[0];
        vb[n][1] = pb[1];
    }

    const float wA[4] = {wa.x, wa.y, wa.z, wa.w};
    const float wB[4] = {wb.x, wb.y, wb.z, wb.w};

    float accA[8] = {0,0,0,0,0,0,0,0};
    float accB[8] = {0,0,0,0,0,0,0,0};
#pragma unroll
    for (int n = 0; n < N_DIM; ++n) {
        const float an = wA[n];
        accA[0] = fmaf(va[n][0].x, an, accA[0]);
        accA[1] = fmaf(va[n][0].y, an, accA[1]);
        accA[2] = fmaf(va[n][0].z, an, accA[2]);
        accA[3] = fmaf(va[n][0].w, an, accA[3]);
        accA[4] = fmaf(va[n][1].x, an, accA[4]);
        accA[5] = fmaf(va[n][1].y, an, accA[5]);
        accA[6] = fmaf(va[n][1].z, an, accA[6]);
        accA[7] = fmaf(va[n][1].w, an, accA[7]);
    }
#pragma unroll
    for (int n = 0; n < N_DIM; ++n) {
        const float bn = wB[n];
        accB[0] = fmaf(vb[n][0].x, bn, accB[0]);
        accB[1] = fmaf(vb[n][0].y, bn, accB[1]);
        accB[2] = fmaf(vb[n][0].z, bn, accB[2]);
        accB[3] = fmaf(vb[n][0].w, bn, accB[3]);
        accB[4] = fmaf(vb[n][1].x, bn, accB[4]);
        accB[5] = fmaf(vb[n][1].y, bn, accB[5]);
        accB[6] = fmaf(vb[n][1].z, bn, accB[6]);
        accB[7] = fmaf(vb[n][1].w, bn, accB[7]);
    }

    // Round through bf16 (reference .astype(bfloat16)), widen to f32, store.
    float4 a0, a1, b0, b1;
    a0.x = __bfloat162float(__float2bfloat16_rn(accA[0]));
    a0.y = __bfloat162float(__float2bfloat16_rn(accA[1]));
    a0.z = __bfloat162float(__float2bfloat16_rn(accA[2]));
    a0.w = __bfloat162float(__float2bfloat16_rn(accA[3]));
    a1.x = __bfloat162float(__float2bfloat16_rn(accA[4]));
    a1.y = __bfloat162float(__float2bfloat16_rn(accA[5]));
    a1.z = __bfloat162float(__float2bfloat16_rn(accA[6]));
    a1.w = __bfloat162float(__float2bfloat16_rn(accA[7]));
    b0.x = __bfloat162float(__float2bfloat16_rn(accB[0]));
    b0.y = __bfloat162float(__float2bfloat16_rn(accB[1]));
    b0.z = __bfloat162float(__float2bfloat16_rn(accB[2]));
    b0.w = __bfloat162float(__float2bfloat16_rn(accB[3]));
    b1.x = __bfloat162float(__float2bfloat16_rn(accB[4]));
    b1.y = __bfloat162float(__float2bfloat16_rn(accB[5]));
    b1.z = __bfloat162float(__float2bfloat16_rn(accB[6]));
    b1.w = __bfloat162float(__float2bfloat16_rn(accB[7]));

    float4* oa = reinterpret_cast<float4*>(out + (size_t)m0 * D_DIM + d0);
    float4* ob = reinterpret_cast<float4*>(out + (size_t)(m0 + 1) * D_DIM + d0);
    oa[0] = a0;
    oa[1] = a1;
    ob[0] = b0;
    ob[1] = b1;
}

extern "C" void kernel_launch(void* const* d_in, const int* in_sizes, int n_in,
                              void* d_out, int out_size)
{
    const float* res;
    const float* h;
    if ((long long)in_sizes[0] == RES_ELEMS) {
        res = (const float*)d_in[0];
        h   = (const float*)d_in[1];
    } else {
        res = (const float*)d_in[1];
        h   = (const float*)d_in[0];
    }

    float* out = (float*)d_out;
    mhc_wsum_f32x2_kernel<<<M_DIM / ROWS_PER_CTA, 512>>>(res, h, out);
}

// round 13
// speedup vs baseline: 1.3916x; 1.0214x over previous
#include <cuda_runtime.h>
#include <cuda_bf16.h>
#include <cstdint>

// World-model (confirmed, rel_err = 0.0):
//   d_in[0] = res  : float32 [M, N, D]   d_in[1] = h_pre: float32 [M, N]
//   d_out   = out  : float32 [M, D]
// out[m,d] = f32( bf16_round( sum_n res[m,n,d] * h[m,n] ) ), fp32 accum.
//
// History: R7 186.3us best (1 row/CTA, 512thr, DRAM 91.5%, 7.25TB/s).
//   R8 cache hints NEUTRAL. R9 persistent FAILED (262us). R10 2 rows/CTA
//   slightly worse (192us; ptxas refused to front-batch 16 loads, regs=34).
// R11: same per-thread body as R7, but 256-thread CTAs covering half a row
//   (grid 32768) — finer scheduling granularity, smoother tail.
static constexpr int M_DIM = 16384;
static constexpr int N_DIM = 4;
static constexpr int D_DIM = 4096;
static constexpr long long RES_ELEMS = (long long)M_DIM * N_DIM * D_DIM;

static constexpr int THREADS     = 256;
static constexpr int HALF_D      = D_DIM / 2;          // 2048 f32 per CTA
static constexpr int CTAS_PER_ROW = 2;

__global__ void __launch_bounds__(THREADS)
mhc_wsum_f32_half_kernel(const float* __restrict__ res,
                         const float* __restrict__ h_pre,
                         float* __restrict__ out)
{
    const int cta  = blockIdx.x;
    const int m    = cta >> 1;                    // row
    const int half = cta & 1;                     // which half of D
    const int t    = threadIdx.x;                 // 0..255
    const int d0   = half * HALF_D + t * 8;       // 8 consecutive f32

    // Per-row weights (16 B, L1-broadcast within the CTA).
    const float4 w4 = *reinterpret_cast<const float4*>(h_pre + (size_t)m * N_DIM);
    const float w[4] = {w4.x, w4.y, w4.z, w4.w};

    const float* base = res + (size_t)m * N_DIM * D_DIM + d0;

    // Front-batch 8 independent 128-bit loads (MLP = 8, zero deps).
    float4 v[N_DIM][2];
#pragma unroll
    for (int n = 0; n < N_DIM; ++n) {
        const float4* p = reinterpret_cast<const float4*>(base + (size_t)n * D_DIM);
        v[n][0] = p[0];
        v[n][1] = p[1];
    }

    float acc[8] = {0,0,0,0,0,0,0,0};
#pragma unroll
    for (int n = 0; n < N_DIM; ++n) {
        const float wn = w[n];
        acc[0] = fmaf(v[n][0].x, wn, acc[0]);
        acc[1] = fmaf(v[n][0].y, wn, acc[1]);
        acc[2] = fmaf(v[n][0].z, wn, acc[2]);
        acc[3] = fmaf(v[n][0].w, wn, acc[3]);
        acc[4] = fmaf(v[n][1].x, wn, acc[4]);
        acc[5] = fmaf(v[n][1].y, wn, acc[5]);
        acc[6] = fmaf(v[n][1].z, wn, acc[6]);
        acc[7] = fmaf(v[n][1].w, wn, acc[7]);
    }

    // Round through bf16 (reference .astype(bfloat16)), widen to f32.
    float4 o0, o1;
    o0.x = __bfloat162float(__float2bfloat16_rn(acc[0]));
    o0.y = __bfloat162float(__float2bfloat16_rn(acc[1]));
    o0.z = __bfloat162float(__float2bfloat16_rn(acc[2]));
    o0.w = __bfloat162float(__float2bfloat16_rn(acc[3]));
    o1.x = __bfloat162float(__float2bfloat16_rn(acc[4]));
    o1.y = __bfloat162float(__float2bfloat16_rn(acc[5]));
    o1.z = __bfloat162float(__float2bfloat16_rn(acc[6]));
    o1.w = __bfloat162float(__float2bfloat16_rn(acc[7]));

    float4* o = reinterpret_cast<float4*>(out + (size_t)m * D_DIM + d0);
    o[0] = o0;
    o[1] = o1;
}

extern "C" void kernel_launch(void* const* d_in, const int* in_sizes, int n_in,
                              void* d_out, int out_size)
{
    const float* res;
    const float* h;
    if ((long long)in_sizes[0] == RES_ELEMS) {
        res = (const float*)d_in[0];
        h   = (const float*)d_in[1];
    } else {
        res = (const float*)d_in[1];
        h   = (const float*)d_in[0];
    }

    float* out = (float*)d_out;
    mhc_wsum_f32_half_kernel<<<M_DIM * CTAS_PER_ROW, THREADS>>>(res, h, out);
}

// round 14
// speedup vs baseline: 1.4054x; 1.0100x over previous
#include <cuda_runtime.h>
#include <cuda_bf16.h>
#include <cstdint>

// FINAL KERNEL (R7 configuration — best of 5 measured structural variants).
//
// World-model (established by 5-round rel_err forensics, confirmed rel_err=0.0):
//   d_in[0] = res  : float32 [M, N, D]  (harness serializes bf16 -> f32, exact)
//   d_in[1] = h_pre: float32 [M, N]
//   d_out   = out  : float32 [M, D]
// out[m,d] = f32( bf16_round( sum_n res[m,n,d] * h[m,n] ) ), fp32 accum.
//
// Measured: 182.8us (ncu), DRAM 91.5%, HBM 7.25 TB/s = 90.6% of spec — at the
// streaming roofline. Alternatives measured and rejected: streaming cache
// hints (neutral), persistent CTAs (+43%, scoreboard serialization),
// 2 rows/CTA (+4%, ptxas de-batches loads), 256-thr half-row CTAs (neutral).
static constexpr int M_DIM = 16384;
static constexpr int N_DIM = 4;
static constexpr int D_DIM = 4096;
static constexpr long long RES_ELEMS = (long long)M_DIM * N_DIM * D_DIM;

// One CTA per row m, 512 threads, 8 consecutive f32 per thread.
// 8 independent LDG.128 front-batched (2 per stream), 32 FMA, 2 STG.128.
__global__ void __launch_bounds__(512, 2)
mhc_wsum_f32_kernel(const float* __restrict__ res,
                    const float* __restrict__ h_pre,
                    float* __restrict__ out)
{
    const int m = blockIdx.x;
    const int t = threadIdx.x;              // 0..511
    const int d0 = t * 8;                   // 8 consecutive d per thread

    // Per-row weights (16 B, L1-broadcast across the CTA).
    const float4 w4 = *reinterpret_cast<const float4*>(h_pre + (size_t)m * N_DIM);
    const float w[4] = {w4.x, w4.y, w4.z, w4.w};

    const float* base = res + (size_t)m * N_DIM * D_DIM + d0;

    // Front-batch 8 independent 128-bit loads for MLP.
    float4 v[N_DIM][2];
#pragma unroll
    for (int n = 0; n < N_DIM; ++n) {
        const float* p = base + (size_t)n * D_DIM;
        v[n][0] = *reinterpret_cast<const float4*>(p);
        v[n][1] = *reinterpret_cast<const float4*>(p + 4);
    }

    float acc[8] = {0,0,0,0,0,0,0,0};
#pragma unroll
    for (int n = 0; n < N_DIM; ++n) {
        const float wn = w[n];
        acc[0] = fmaf(v[n][0].x, wn, acc[0]);
        acc[1] = fmaf(v[n][0].y, wn, acc[1]);
        acc[2] = fmaf(v[n][0].z, wn, acc[2]);
        acc[3] = fmaf(v[n][0].w, wn, acc[3]);
        acc[4] = fmaf(v[n][1].x, wn, acc[4]);
        acc[5] = fmaf(v[n][1].y, wn, acc[5]);
        acc[6] = fmaf(v[n][1].z, wn, acc[6]);
        acc[7] = fmaf(v[n][1].w, wn, acc[7]);
    }

    // Round through bf16 (matches reference .astype(bfloat16)), widen to f32.
    float r[8];
#pragma unroll
    for (int j = 0; j < 8; ++j) {
        r[j] = __bfloat162float(__float2bfloat16_rn(acc[j]));
    }

    float* o = out + (size_t)m * D_DIM + d0;
    *reinterpret_cast<float4*>(o)     = make_float4(r[0], r[1], r[2], r[3]);
    *reinterpret_cast<float4*>(o + 4) = make_float4(r[4], r[5], r[6], r[7]);
}

extern "C" void kernel_launch(void* const* d_in, const int* in_sizes, int n_in,
                              void* d_out, int out_size)
{
    const float* res;
    const float* h;
    if ((long long)in_sizes[0] == RES_ELEMS) {
        res = (const float*)d_in[0];
        h   = (const float*)d_in[1];
    } else {
        res = (const float*)d_in[1];
        h   = (const float*)d_in[0];
    }

    float* out = (float*)d_out;
    mhc_wsum_f32_kernel<<<M_DIM, 512>>>(res, h, out);
}

// round 15
// speedup vs baseline: 1.4076x; 1.0015x over previous
#include <cuda_runtime.h>
#include <cuda_bf16.h>
#include <cstdint>

// World-model (confirmed, rel_err = 0.0 across all passing rounds):
//   d_in[0] = res  : float32 [M, N, D]   d_in[1] = h_pre: float32 [M, N]
//   d_out   = out  : float32 [M, D]
// out[m,d] = f32( bf16_round( sum_n res[m,n,d] * h[m,n] ) ), fp32 accum.
//
// R13 change vs best (R7, 186.3us, DRAM 91%): Blackwell 256-bit memory ops
// (PTX 8.7 ld/st.global.v8.f32, sm_100+). 4 loads + 1 store per thread
// instead of 8 + 2 — halves LSU transactions / L1tex wavefronts per byte.
static constexpr int M_DIM = 16384;
static constexpr int N_DIM = 4;
static constexpr int D_DIM = 4096;
static constexpr long long RES_ELEMS = (long long)M_DIM * N_DIM * D_DIM;

struct alignas(32) f32x8 { float v[8]; };

__device__ __forceinline__ f32x8 ldg_v8(const float* p) {
    f32x8 r;
    asm volatile("ld.global.v8.f32 {%0,%1,%2,%3,%4,%5,%6,%7}, [%8];"
                 : "=f"(r.v[0]), "=f"(r.v[1]), "=f"(r.v[2]), "=f"(r.v[3]),
                   "=f"(r.v[4]), "=f"(r.v[5]), "=f"(r.v[6]), "=f"(r.v[7])
                 : "l"(p));
    return r;
}

__device__ __forceinline__ void stg_v8(float* p, const f32x8& r) {
    asm volatile("st.global.v8.f32 [%0], {%1,%2,%3,%4,%5,%6,%7,%8};"
                 :: "l"(p),
                    "f"(r.v[0]), "f"(r.v[1]), "f"(r.v[2]), "f"(r.v[3]),
                    "f"(r.v[4]), "f"(r.v[5]), "f"(r.v[6]), "f"(r.v[7])
                 : "memory");
}

// One CTA per row m, 512 threads, 8 consecutive f32 (32 B) per thread.
// 4 independent 256-bit loads (one per stream), 32 FMA, 1 256-bit store.
__global__ void __launch_bounds__(512, 2)
mhc_wsum_v8_kernel(const float* __restrict__ res,
                   const float* __restrict__ h_pre,
                   float* __restrict__ out)
{
    const int m = blockIdx.x;
    const int t = threadIdx.x;              // 0..511
    const int d0 = t * 8;                   // 32-byte aligned

    // Per-row weights (16 B, L1-broadcast across the CTA).
    const float4 w4 = *reinterpret_cast<const float4*>(h_pre + (size_t)m * N_DIM);
    const float w[4] = {w4.x, w4.y, w4.z, w4.w};

    const float* base = res + (size_t)m * N_DIM * D_DIM + d0;

    // Front-batch 4 independent 256-bit loads (one per stream, 8 KiB apart).
    f32x8 v[N_DIM];
#pragma unroll
    for (int n = 0; n < N_DIM; ++n) {
        v[n] = ldg_v8(base + (size_t)n * D_DIM);
    }

    float acc[8] = {0,0,0,0,0,0,0,0};
#pragma unroll
    for (int n = 0; n < N_DIM; ++n) {
        const float wn = w[n];
#pragma unroll
        for (int j = 0; j < 8; ++j) {
            acc[j] = fmaf(v[n].v[j], wn, acc[j]);
        }
    }

    // Round through bf16 (reference .astype(bfloat16)), widen to f32.
    f32x8 r;
#pragma unroll
    for (int j = 0; j < 8; ++j) {
        r.v[j] = __bfloat162float(__float2bfloat16_rn(acc[j]));
    }

    stg_v8(out + (size_t)m * D_DIM + d0, r);
}

extern "C" void kernel_launch(void* const* d_in, const int* in_sizes, int n_in,
                              void* d_out, int out_size)
{
    const float* res;
    const float* h;
    if ((long long)in_sizes[0] == RES_ELEMS) {
        res = (const float*)d_in[0];
        h   = (const float*)d_in[1];
    } else {
        res = (const float*)d_in[1];
        h   = (const float*)d_in[0];
    }

    float* out = (float*)d_out;
    mhc_wsum_v8_kernel<<<M_DIM, 512>>>(res, h, out);
}